// round 7
// baseline (speedup 1.0000x reference)
#include <cuda_runtime.h>
#include <cuda_bf16.h>
#include <math.h>
#include <stdint.h>

#define D    128
#define Bn   4
#define NSn  10000
#define NTn  10000
#define En   160000
#define Kc   16
#define LDS_T 136   // padded bf16 row (272B)
#define LDC   132
#define NT32 20000              // (Bn*En)/32 tiles
#define XIMG_TILE 17408         // 32*136*2*2 (hi+lo)

// ---------------- scratch ----------------
__device__ float g_Ps  [Bn * NSn * D];
__device__ float g_Pt  [Bn * NTn * D];
__device__ float g_Ptt [Bn * NTn * D];
__device__ float g_db  [Bn * En  * D];
__device__ float g_red [Bn * NTn * D];
__device__ __nv_bfloat16 g_Wh[5 * D * D];   // 0=W_s2e 1=W_t2e 2=W_e2e 3=W_e2t 4=W_t2t
__device__ __nv_bfloat16 g_Wl[5 * D * D];
__device__ uint4 g_Ximg[(size_t)NT32 * XIMG_TILE / 16];   // pre-split bond tiles (hi|lo)

// ---------------- PTX helpers ----------------
__device__ __forceinline__ uint32_t smem_u32(const void* p) {
    return (uint32_t)__cvta_generic_to_shared(p);
}
__device__ __forceinline__ void ldsm4(uint32_t a, uint32_t r[4]) {
    asm volatile("ldmatrix.sync.aligned.m8n8.x4.shared.b16 {%0,%1,%2,%3}, [%4];"
                 : "=r"(r[0]), "=r"(r[1]), "=r"(r[2]), "=r"(r[3]) : "r"(a));
}
__device__ __forceinline__ void ldsm4t(uint32_t a, uint32_t r[4]) {
    asm volatile("ldmatrix.sync.aligned.m8n8.x4.trans.shared.b16 {%0,%1,%2,%3}, [%4];"
                 : "=r"(r[0]), "=r"(r[1]), "=r"(r[2]), "=r"(r[3]) : "r"(a));
}
__device__ __forceinline__ void mma16816(float c[4], const uint32_t a[4],
                                         uint32_t b0, uint32_t b1) {
    asm volatile("mma.sync.aligned.m16n8k16.row.col.f32.bf16.bf16.f32 "
                 "{%0,%1,%2,%3},{%4,%5,%6,%7},{%8,%9},{%0,%1,%2,%3};"
                 : "+f"(c[0]), "+f"(c[1]), "+f"(c[2]), "+f"(c[3])
                 : "r"(a[0]), "r"(a[1]), "r"(a[2]), "r"(a[3]), "r"(b0), "r"(b1));
}
__device__ __forceinline__ void cp16(uint32_t dst, const void* src) {
    asm volatile("cp.async.cg.shared.global [%0], [%1], 16;" :: "r"(dst), "l"(src));
}
__device__ __forceinline__ void cp_commit() { asm volatile("cp.async.commit_group;"); }
__device__ __forceinline__ void cp_wait0()  { asm volatile("cp.async.wait_group 0;"); }
__device__ __forceinline__ void cp_wait1()  { asm volatile("cp.async.wait_group 1;"); }
__device__ __forceinline__ void split2(float2 v, uint32_t& hi, uint32_t& lo) {
    __nv_bfloat16 hx = __float2bfloat16(v.x), hy = __float2bfloat16(v.y);
    __nv_bfloat162 h; h.x = hx; h.y = hy;
    __nv_bfloat162 l;
    l.x = __float2bfloat16(v.x - __bfloat162float(hx));
    l.y = __float2bfloat16(v.y - __bfloat162float(hy));
    hi = *(uint32_t*)&h;
    lo = *(uint32_t*)&l;
}
__device__ __forceinline__ float silu_f(float x) { return x / (1.0f + __expf(-x)); }

// ---------------- weight pre-split ----------------
__global__ __launch_bounds__(256) void prep_w_kernel(const float* __restrict__ W0,
                                                     const float* __restrict__ W1,
                                                     const float* __restrict__ W2,
                                                     const float* __restrict__ W3,
                                                     const float* __restrict__ W4) {
    int i = blockIdx.x * 256 + threadIdx.x;
    int w = i >> 14, j = i & (D * D - 1);
    const float* W = (w == 0) ? W0 : (w == 1) ? W1 : (w == 2) ? W2 : (w == 3) ? W3 : W4;
    float x = W[j];
    __nv_bfloat16 h = __float2bfloat16(x);
    g_Wh[i] = h;
    g_Wl[i] = __float2bfloat16(x - __bfloat162float(h));
}

// ---------------- bond pre-split into tile images ----------------
__global__ __launch_bounds__(256) void prep_x_kernel(const float* __restrict__ bond) {
    int idx = blockIdx.x * 256 + threadIdx.x;   // one thread per 8 floats
    int gr = idx >> 4;                          // global row
    int c  = (idx & 15) * 8;
    int t  = gr >> 5, r = gr & 31;
    const float* sp = bond + (size_t)gr * D + c;
    float4 v0 = *(const float4*)(sp);
    float4 v1 = *(const float4*)(sp + 4);
    uint32_t h0, l0, h1, l1, h2, l2, h3, l3;
    split2(make_float2(v0.x, v0.y), h0, l0);
    split2(make_float2(v0.z, v0.w), h1, l1);
    split2(make_float2(v1.x, v1.y), h2, l2);
    split2(make_float2(v1.z, v1.w), h3, l3);
    char* img = (char*)g_Ximg + (size_t)t * XIMG_TILE;
    *(uint4*)(img + r * 272 + c * 2)        = make_uint4(h0, h1, h2, h3);
    *(uint4*)(img + 8704 + r * 272 + c * 2) = make_uint4(l0, l1, l2, l3);
}

// ---------------- shared HMMA pieces for small kernels (R2/R6-proven) ----------------
__device__ __forceinline__ void load_W_cp(__nv_bfloat16* Wh, __nv_bfloat16* Wl, int widx, int tid) {
    const __nv_bfloat16* gh = g_Wh + widx * D * D;
    const __nv_bfloat16* gl = g_Wl + widx * D * D;
    uint32_t dh = smem_u32(Wh), dl = smem_u32(Wl);
    #pragma unroll
    for (int i = tid; i < D * 16; i += 256) {
        int r = i >> 4, c = (i & 15) * 8;
        uint32_t o = (uint32_t)(r * LDS_T + c) * 2;
        cp16(dh + o, gh + r * D + c);
        cp16(dl + o, gl + r * D + c);
    }
}
__device__ __forceinline__ void load_X_split(__nv_bfloat16* Xh, __nv_bfloat16* Xl,
                                             const float* __restrict__ Xg, int tid) {
    #pragma unroll
    for (int i = tid; i < 64 * 32; i += 256) {
        int r = i >> 5, c = (i & 31) * 4;
        float4 v = *(const float4*)(Xg + (size_t)r * D + c);
        uint32_t h0, l0, h1, l1;
        split2(make_float2(v.x, v.y), h0, l0);
        split2(make_float2(v.z, v.w), h1, l1);
        *(uint32_t*)(Xh + r * LDS_T + c)     = h0;
        *(uint32_t*)(Xh + r * LDS_T + c + 2) = h1;
        *(uint32_t*)(Xl + r * LDS_T + c)     = l0;
        *(uint32_t*)(Xl + r * LDS_T + c + 2) = l1;
    }
}
#define KOFF ((uint32_t)(16 * LDS_T * 2))

__device__ __forceinline__ void gemm_mma64(const __nv_bfloat16* Xh, const __nv_bfloat16* Xl,
                                           const __nv_bfloat16* Wh, const __nv_bfloat16* Wl,
                                           int tid, float acc[8][4]) {
    int lane = tid & 31, w = tid >> 5;
    int rg = (w & 3) * 16, cg = (w >> 2) * 64;
    #pragma unroll
    for (int i = 0; i < 8; i++)
        #pragma unroll
        for (int j = 0; j < 4; j++) acc[i][j] = 0.0f;
    int l7 = lane & 7, lm = lane >> 3;
    int a_cad = (lm >> 1) << 3;
    uint32_t aH = smem_u32(Xh + (rg + l7 + ((lm & 1) << 3)) * LDS_T + a_cad);
    uint32_t aL = smem_u32(Xl + (rg + l7 + ((lm & 1) << 3)) * LDS_T + a_cad);
    int b_krow = l7 + ((lm & 1) << 3);
    uint32_t bHb[4], bLb[4];
    #pragma unroll
    for (int nr = 0; nr < 4; nr++) {
        int col = cg + nr * 16 + a_cad;
        bHb[nr] = smem_u32(Wh + b_krow * LDS_T + col);
        bLb[nr] = smem_u32(Wl + b_krow * LDS_T + col);
    }
    #pragma unroll
    for (int k = 0; k < 8; k++) {
        uint32_t AH[4], AL[4];
        ldsm4(aH + (uint32_t)k * 32, AH);
        ldsm4(aL + (uint32_t)k * 32, AL);
        #pragma unroll
        for (int nr = 0; nr < 4; nr++) {
            uint32_t BH[4], BL[4];
            ldsm4t(bHb[nr] + (uint32_t)k * KOFF, BH);
            ldsm4t(bLb[nr] + (uint32_t)k * KOFF, BL);
            mma16816(acc[2 * nr],     AH, BH[0], BH[1]);
            mma16816(acc[2 * nr],     AH, BL[0], BL[1]);
            mma16816(acc[2 * nr],     AL, BH[0], BH[1]);
            mma16816(acc[2 * nr + 1], AH, BH[2], BH[3]);
            mma16816(acc[2 * nr + 1], AH, BL[2], BL[3]);
            mma16816(acc[2 * nr + 1], AL, BH[2], BH[3]);
        }
    }
}
__device__ __forceinline__ void stage_acc(float* Cs, const float acc[8][4], int tid) {
    int lane = tid & 31, w = tid >> 5;
    int rg = (w & 3) * 16, cg = (w >> 2) * 64;
    int gid = lane >> 2, tid4 = lane & 3;
    #pragma unroll
    for (int nt = 0; nt < 8; nt++) {
        int col = cg + nt * 8 + tid4 * 2;
        int row = rg + gid;
        *(float2*)(Cs + row * LDC + col)       = make_float2(acc[nt][0], acc[nt][1]);
        *(float2*)(Cs + (row + 8) * LDC + col) = make_float2(acc[nt][2], acc[nt][3]);
    }
}
__device__ __forceinline__ void silu_ln(float v[4], const float gg[4], const float bb[4],
                                        float out[4]) {
    #pragma unroll
    for (int c = 0; c < 4; c++) v[c] = silu_f(v[c]);
    float s1 = v[0] + v[1] + v[2] + v[3];
    float s2 = v[0]*v[0] + v[1]*v[1] + v[2]*v[2] + v[3]*v[3];
    #pragma unroll
    for (int o = 16; o > 0; o >>= 1) {
        s1 += __shfl_xor_sync(0xFFFFFFFFu, s1, o);
        s2 += __shfl_xor_sync(0xFFFFFFFFu, s2, o);
    }
    float m   = s1 * (1.0f / D);
    float var = fmaxf(s2 * (1.0f / D) - m * m, 0.0f);
    float rs  = rsqrtf(var + 1e-5f);
    #pragma unroll
    for (int c = 0; c < 4; c++) out[c] = (v[c] - m) * rs * gg[c] + bb[c];
}

#define SM_SINGLE ((2 * 64 * LDS_T + 2 * D * LDS_T) * 2)
#define SM_DUAL   ((2 * 64 * LDS_T + 4 * D * LDS_T) * 2)

// ---------------- kernel 1: src @ W_s2e -> g_Ps ----------------
__global__ __launch_bounds__(256, 2) void proj_src_kernel(const float* __restrict__ src) {
    extern __shared__ char sm[];
    __nv_bfloat16* Xh = (__nv_bfloat16*)sm;
    __nv_bfloat16* Xl = Xh + 64 * LDS_T;
    __nv_bfloat16* Wh = Xl + 64 * LDS_T;
    __nv_bfloat16* Wl = Wh + D * LDS_T;
    float* Cs = (float*)sm;
    int tid = threadIdx.x;
    int row0 = blockIdx.x * 64;
    load_W_cp(Wh, Wl, 0, tid);
    cp_commit();
    load_X_split(Xh, Xl, src + (size_t)row0 * D, tid);
    cp_wait0();
    __syncthreads();
    float acc[8][4];
    gemm_mma64(Xh, Xl, Wh, Wl, tid, acc);
    __syncthreads();
    stage_acc(Cs, acc, tid);
    __syncthreads();
    int tx = tid & 31, ty = tid >> 5;
    #pragma unroll
    for (int r = 0; r < 8; r++) {
        float4 v = *(float4*)(Cs + (ty * 8 + r) * LDC + tx * 4);
        *(float4*)(g_Ps + (size_t)(row0 + ty * 8 + r) * D + tx * 4) = v;
    }
}

// ---------------- kernel 2: tgt dual proj ----------------
__global__ __launch_bounds__(256) void proj_tgt_dual_kernel(const float* __restrict__ tgt) {
    extern __shared__ char sm[];
    __nv_bfloat16* Xh  = (__nv_bfloat16*)sm;
    __nv_bfloat16* Xl  = Xh + 64 * LDS_T;
    __nv_bfloat16* Wh1 = Xl + 64 * LDS_T;
    __nv_bfloat16* Wl1 = Wh1 + D * LDS_T;
    __nv_bfloat16* Wh2 = Wl1 + D * LDS_T;
    __nv_bfloat16* Wl2 = Wh2 + D * LDS_T;
    float* Cs = (float*)Wh1;
    int tid = threadIdx.x;
    int row0 = blockIdx.x * 64;
    load_W_cp(Wh1, Wl1, 1, tid);
    load_W_cp(Wh2, Wl2, 4, tid);
    cp_commit();
    load_X_split(Xh, Xl, tgt + (size_t)row0 * D, tid);
    cp_wait0();
    __syncthreads();
    int tx = tid & 31, ty = tid >> 5;
    {
        float acc[8][4];
        gemm_mma64(Xh, Xl, Wh1, Wl1, tid, acc);
        __syncthreads();
        stage_acc(Cs, acc, tid);
        __syncthreads();
        #pragma unroll
        for (int r = 0; r < 8; r++) {
            float4 v = *(float4*)(Cs + (ty * 8 + r) * LDC + tx * 4);
            *(float4*)(g_Pt + (size_t)(row0 + ty * 8 + r) * D + tx * 4) = v;
        }
        __syncthreads();
    }
    {
        float acc[8][4];
        gemm_mma64(Xh, Xl, Wh2, Wl2, tid, acc);
        __syncthreads();
        stage_acc(Cs, acc, tid);
        __syncthreads();
        #pragma unroll
        for (int r = 0; r < 8; r++) {
            float4 v = *(float4*)(Cs + (ty * 8 + r) * LDC + tx * 4);
            *(float4*)(g_Ptt + (size_t)(row0 + ty * 8 + r) * D + tx * 4) = v;
        }
    }
}

// ================= persistent pipelined bond kernel (32-row tiles) =================
// smem layout (bytes):
#define BWH    0
#define BWL    34816
#define BX(b)  (69632 + (b) * 17408)
#define BPART  104448
#define BSG    105472
#define BSB    105984
#define SM_BONDP 106496

__global__ __launch_bounds__(256, 2) void bond_kernel(const float* __restrict__ g1,
        const float* __restrict__ b1, const int* __restrict__ src_order,
        const int* __restrict__ tgt_order, float* __restrict__ out0) {
    extern __shared__ char sm[];
    uint32_t smb = smem_u32(sm);
    int tid = threadIdx.x, lane = tid & 31, wid = tid >> 5;
    int rg = wid & 1, cg = wid >> 1;             // 2 m-tiles x 4 col-groups
    int G = gridDim.x, bid = blockIdx.x;
    __nv_bfloat16* Wh = (__nv_bfloat16*)(sm + BWH);
    __nv_bfloat16* Wl = (__nv_bfloat16*)(sm + BWL);

    load_W_cp(Wh, Wl, 2, tid);   // W_e2e, async (part of group0)
    if (tid < D) {
        ((float*)(sm + BSG))[tid] = g1[tid];
        ((float*)(sm + BSB))[tid] = b1[tid];
    }

    int n = (NT32 - bid + G - 1) / G;
    // prefetch tile 0 (group0 with W) and tile 1 (group1)
    if (n > 0) {
        const char* src = (const char*)g_Ximg + (size_t)bid * XIMG_TILE;
        #pragma unroll
        for (int j = tid; j < 1088; j += 256) cp16(smb + BX(0) + j * 16, src + (size_t)j * 16);
    }
    cp_commit();
    if (n > 1) {
        const char* src = (const char*)g_Ximg + (size_t)(bid + G) * XIMG_TILE;
        #pragma unroll
        for (int j = tid; j < 1088; j += 256) cp16(smb + BX(1) + j * 16, src + (size_t)j * 16);
    }
    cp_commit();

    // fragment bases
    int l7 = lane & 7, lm = lane >> 3;
    int a_cad = (lm >> 1) << 3;
    uint32_t a_row_off = (uint32_t)((rg * 16 + l7 + ((lm & 1) << 3)) * LDS_T + a_cad) * 2;
    int b_krow = l7 + ((lm & 1) << 3);
    uint32_t bHb[2], bLb[2];
    #pragma unroll
    for (int nr = 0; nr < 2; nr++) {
        int col = cg * 32 + nr * 16 + a_cad;
        bHb[nr] = smem_u32(Wh + b_krow * LDS_T + col);
        bLb[nr] = smem_u32(Wl + b_krow * LDS_T + col);
    }
    int g = lane >> 2, t4 = lane & 3;
    int c0 = cg * 32 + t4 * 2;
    float* partials = (float*)(sm + BPART);
    const float* sG = (const float*)(sm + BSG);
    const float* sB = (const float*)(sm + BSB);

    for (int i = 0; i < n; i++) {
        cp_wait1();
        __syncthreads();
        int cb = i & 1;
        uint32_t xh = smb + BX(cb);
        uint32_t xl = xh + 8704;

        // ---- MMA: 32x128 tile ----
        float acc[4][4];
        #pragma unroll
        for (int a = 0; a < 4; a++)
            #pragma unroll
            for (int j = 0; j < 4; j++) acc[a][j] = 0.0f;
        #pragma unroll
        for (int k = 0; k < 8; k++) {
            uint32_t AH[4], AL[4];
            ldsm4(xh + a_row_off + (uint32_t)k * 32, AH);
            ldsm4(xl + a_row_off + (uint32_t)k * 32, AL);
            #pragma unroll
            for (int nr = 0; nr < 2; nr++) {
                uint32_t BH[4], BL[4];
                ldsm4t(bHb[nr] + (uint32_t)k * KOFF, BH);
                ldsm4t(bLb[nr] + (uint32_t)k * KOFF, BL);
                mma16816(acc[2 * nr],     AH, BH[0], BH[1]);
                mma16816(acc[2 * nr],     AH, BL[0], BL[1]);
                mma16816(acc[2 * nr],     AL, BH[0], BH[1]);
                mma16816(acc[2 * nr + 1], AH, BH[2], BH[3]);
                mma16816(acc[2 * nr + 1], AH, BL[2], BL[3]);
                mma16816(acc[2 * nr + 1], AL, BH[2], BH[3]);
            }
        }

        // ---- epilogue ----
        size_t grow0 = (size_t)(bid + (size_t)i * G) * 32;
        int bb = (int)(grow0 / En);
        int ebase = (int)(grow0 - (size_t)bb * En);
        const float* PsB = g_Ps + (size_t)bb * NSn * D;
        const float* PtB = g_Pt + (size_t)bb * NTn * D;

        #pragma unroll
        for (int rp = 0; rp < 2; rp++) {
            int r = rg * 16 + g + rp * 8;
            int e = ebase + r;
            const float* ps = PsB + (size_t)src_order[e] * D;
            const float* pt = PtB + (size_t)tgt_order[e] * D;
            float s1 = 0.f, s2 = 0.f;
            int j = rp * 2;
            #pragma unroll
            for (int q = 0; q < 4; q++) {
                int c = c0 + q * 8;
                float2 p  = *(const float2*)(ps + c);
                float2 qv = *(const float2*)(pt + c);
                float v0 = silu_f(acc[q][j]     + p.x + qv.x);
                float v1 = silu_f(acc[q][j + 1] + p.y + qv.y);
                acc[q][j] = v0; acc[q][j + 1] = v1;
                s1 += v0 + v1;
                s2 += v0 * v0 + v1 * v1;
            }
            s1 += __shfl_xor_sync(0xFFFFFFFFu, s1, 1);
            s2 += __shfl_xor_sync(0xFFFFFFFFu, s2, 1);
            s1 += __shfl_xor_sync(0xFFFFFFFFu, s1, 2);
            s2 += __shfl_xor_sync(0xFFFFFFFFu, s2, 2);
            if (t4 == 0)
                *(float2*)(partials + (r * 4 + cg) * 2) = make_float2(s1, s2);
        }
        __syncthreads();

        #pragma unroll
        for (int rp = 0; rp < 2; rp++) {
            int r = rg * 16 + g + rp * 8;
            float2 p0 = *(float2*)(partials + (r * 4 + 0) * 2);
            float2 p1 = *(float2*)(partials + (r * 4 + 1) * 2);
            float2 p2 = *(float2*)(partials + (r * 4 + 2) * 2);
            float2 p3 = *(float2*)(partials + (r * 4 + 3) * 2);
            float S1 = p0.x + p1.x + p2.x + p3.x;
            float S2 = p0.y + p1.y + p2.y + p3.y;
            float mM = S1 * (1.0f / D);
            float rs = rsqrtf(fmaxf(S2 * (1.0f / D) - mM * mM, 0.0f) + 1e-5f);
            float* db = g_db + (grow0 + r) * D;
            float* oo = out0 + (grow0 + r) * D;
            const char* xrh = sm + BX(cb) + r * 272;
            const char* xrl = xrh + 8704;
            int j = rp * 2;
            #pragma unroll
            for (int q = 0; q < 4; q++) {
                int c = c0 + q * 8;
                float2 gg = *(const float2*)(sG + c);
                float2 be = *(const float2*)(sB + c);
                __nv_bfloat162 H = *(const __nv_bfloat162*)(xrh + c * 2);
                __nv_bfloat162 L = *(const __nv_bfloat162*)(xrl + c * 2);
                float x0 = __bfloat162float(H.x) + __bfloat162float(L.x);
                float x1 = __bfloat162float(H.y) + __bfloat162float(L.y);
                float d0 = (acc[q][j]     - mM) * rs * gg.x + be.x;
                float d1 = (acc[q][j + 1] - mM) * rs * gg.y + be.y;
                *(float2*)(db + c) = make_float2(d0, d1);
                *(float2*)(oo + c) = make_float2(x0 + d0, x1 + d1);
            }
        }
        __syncthreads();

        // prefetch tile i+2 into the buffer we just freed
        if (i + 2 < n) {
            const char* src = (const char*)g_Ximg + (size_t)(bid + (size_t)(i + 2) * G) * XIMG_TILE;
            #pragma unroll
            for (int j = tid; j < 1088; j += 256) cp16(smb + BX(cb) + j * 16, src + (size_t)j * 16);
        }
        cp_commit();
    }
}

// ---------------- kernel 4: bond_reduce ----------------
__global__ __launch_bounds__(256) void reduce_kernel(const int* __restrict__ edge_order,
                                                     const float* __restrict__ coef) {
    int tid  = threadIdx.x;
    int lane = tid & 31;
    int node = (blockIdx.x * blockDim.x + tid) >> 5;
    int b = node / NTn;
    int t = node - b * NTn;
    int   e_l = 0;
    float c_l = 0.0f;
    if (lane < Kc) {
        e_l = edge_order[t * Kc + lane];
        c_l = coef[t * Kc + lane];
    }
    float4 acc = {0.f, 0.f, 0.f, 0.f};
    #pragma unroll
    for (int k = 0; k < Kc; k++) {
        int   e = __shfl_sync(0xFFFFFFFFu, e_l, k);
        float c = __shfl_sync(0xFFFFFFFFu, c_l, k);
        float4 v = *(const float4*)(g_db + ((size_t)b * En + e) * D + lane * 4);
        acc.x += c * v.x;
        acc.y += c * v.y;
        acc.z += c * v.z;
        acc.w += c * v.w;
    }
    const float inv = 1.0f / Kc;
    acc.x *= inv; acc.y *= inv; acc.z *= inv; acc.w *= inv;
    *(float4*)(g_red + (size_t)node * D + lane * 4) = acc;
}

// ---------------- kernel 5: d_tgt ----------------
__global__ __launch_bounds__(256, 2) void tgt_kernel(const float* __restrict__ tgt,
                                                     const float* __restrict__ g2,
                                                     const float* __restrict__ b2,
                                                     float* __restrict__ out2) {
    extern __shared__ char sm[];
    __nv_bfloat16* Xh = (__nv_bfloat16*)sm;
    __nv_bfloat16* Xl = Xh + 64 * LDS_T;
    __nv_bfloat16* Wh = Xl + 64 * LDS_T;
    __nv_bfloat16* Wl = Wh + D * LDS_T;
    float* Cs = (float*)sm;
    int tid = threadIdx.x;
    int row0 = blockIdx.x * 64;
    load_W_cp(Wh, Wl, 3, tid);
    cp_commit();
    load_X_split(Xh, Xl, g_red + (size_t)row0 * D, tid);
    cp_wait0();
    __syncthreads();
    float acc[8][4];
    gemm_mma64(Xh, Xl, Wh, Wl, tid, acc);
    __syncthreads();
    stage_acc(Cs, acc, tid);
    __syncthreads();

    int tx = tid & 31, ty = tid >> 5;
    float gg[4], bb[4];
    #pragma unroll
    for (int c = 0; c < 4; c++) { gg[c] = g2[tx * 4 + c]; bb[c] = b2[tx * 4 + c]; }
    #pragma unroll
    for (int r = 0; r < 8; r++) {
        int row = row0 + ty * 8 + r;
        float4 cv = *(float4*)(Cs + (ty * 8 + r) * LDC + tx * 4);
        float4 pt = *(const float4*)(g_Ptt + (size_t)row * D + tx * 4);
        float v[4];
        v[0] = cv.x + pt.x;
        v[1] = cv.y + pt.y;
        v[2] = cv.z + pt.z;
        v[3] = cv.w + pt.w;
        float d[4];
        silu_ln(v, gg, bb, d);
        float4 tin = *(const float4*)(tgt + (size_t)row * D + tx * 4);
        float4 o2 = {tin.x + d[0], tin.y + d[1], tin.z + d[2], tin.w + d[3]};
        *(float4*)(out2 + (size_t)row * D + tx * 4) = o2;
    }
}

// ---------------- launch ----------------
extern "C" void kernel_launch(void* const* d_in, const int* in_sizes, int n_in,
                              void* d_out, int out_size) {
    const float* bond  = (const float*)d_in[0];
    const float* src   = (const float*)d_in[1];
    const float* tgt   = (const float*)d_in[2];
    const float* W_s2e = (const float*)d_in[3];
    const float* W_t2e = (const float*)d_in[4];
    const float* W_e2e = (const float*)d_in[5];
    const float* ln1_g = (const float*)d_in[6];
    const float* ln1_b = (const float*)d_in[7];
    const float* W_e2t = (const float*)d_in[8];
    const float* W_t2t = (const float*)d_in[9];
    const float* ln2_g = (const float*)d_in[10];
    const float* ln2_b = (const float*)d_in[11];
    const float* coef  = (const float*)d_in[12];
    const int*   so    = (const int*)d_in[13];
    const int*   to    = (const int*)d_in[14];
    const int*   eo    = (const int*)d_in[15];

    float* out  = (float*)d_out;
    float* out0 = out;
    float* out1 = out0 + (size_t)Bn * En * D;
    float* out2 = out1 + (size_t)Bn * NSn * D;

    int nsm = 148;
    cudaDeviceGetAttribute(&nsm, cudaDevAttrMultiProcessorCount, 0);

    cudaFuncSetAttribute(proj_src_kernel,      cudaFuncAttributeMaxDynamicSharedMemorySize, SM_SINGLE);
    cudaFuncSetAttribute(proj_tgt_dual_kernel, cudaFuncAttributeMaxDynamicSharedMemorySize, SM_DUAL);
    cudaFuncSetAttribute(bond_kernel,          cudaFuncAttributeMaxDynamicSharedMemorySize, SM_BONDP);
    cudaFuncSetAttribute(tgt_kernel,           cudaFuncAttributeMaxDynamicSharedMemorySize, SM_SINGLE);

    prep_w_kernel<<<320, 256>>>(W_s2e, W_t2e, W_e2e, W_e2t, W_t2t);
    prep_x_kernel<<<40000, 256>>>(bond);

    proj_src_kernel<<<(Bn * NSn) / 64, 256, SM_SINGLE>>>(src);
    proj_tgt_dual_kernel<<<(Bn * NTn) / 64, 256, SM_DUAL>>>(tgt);

    cudaMemcpyAsync(out1, src, (size_t)Bn * NSn * D * sizeof(float),
                    cudaMemcpyDeviceToDevice, 0);

    bond_kernel<<<2 * nsm, 256, SM_BONDP>>>(ln1_g, ln1_b, so, to, out0);

    reduce_kernel<<<(Bn * NTn) / 8, 256>>>(eo, coef);

    tgt_kernel<<<(Bn * NTn) / 64, 256, SM_SINGLE>>>(tgt, ln2_g, ln2_b, out2);
}

// round 8
// speedup vs baseline: 1.3096x; 1.3096x over previous
#include <cuda_runtime.h>
#include <cuda_fp16.h>
#include <math.h>
#include <stdint.h>

#define D    128
#define Bn   4
#define NSn  10000
#define NTn  10000
#define En   160000
#define Kc   16
#define LDS_T 136   // padded fp16 row (272B, 16B-aligned, ldmatrix conflict-free)
#define LDC   132   // padded fp32 C row

// ---------------- scratch ----------------
__device__ float g_Ps  [Bn * NSn * D];
__device__ float g_Pt  [Bn * NTn * D];
__device__ float g_Ptt [Bn * NTn * D];
__device__ float g_db  [Bn * En  * D];
__device__ float g_red [Bn * NTn * D];
__device__ __half g_Wh[5 * D * D];   // 0=W_s2e 1=W_t2e 2=W_e2e 3=W_e2t 4=W_t2t
__device__ __half g_Wl[5 * D * D];

// ---------------- PTX helpers ----------------
__device__ __forceinline__ uint32_t smem_u32(const void* p) {
    return (uint32_t)__cvta_generic_to_shared(p);
}
__device__ __forceinline__ void ldsm4(uint32_t a, uint32_t r[4]) {
    asm volatile("ldmatrix.sync.aligned.m8n8.x4.shared.b16 {%0,%1,%2,%3}, [%4];"
                 : "=r"(r[0]), "=r"(r[1]), "=r"(r[2]), "=r"(r[3]) : "r"(a));
}
__device__ __forceinline__ void ldsm4t(uint32_t a, uint32_t r[4]) {
    asm volatile("ldmatrix.sync.aligned.m8n8.x4.trans.shared.b16 {%0,%1,%2,%3}, [%4];"
                 : "=r"(r[0]), "=r"(r[1]), "=r"(r[2]), "=r"(r[3]) : "r"(a));
}
__device__ __forceinline__ void mma16816(float c[4], const uint32_t a[4],
                                         uint32_t b0, uint32_t b1) {
    asm volatile("mma.sync.aligned.m16n8k16.row.col.f32.f16.f16.f32 "
                 "{%0,%1,%2,%3},{%4,%5,%6,%7},{%8,%9},{%0,%1,%2,%3};"
                 : "+f"(c[0]), "+f"(c[1]), "+f"(c[2]), "+f"(c[3])
                 : "r"(a[0]), "r"(a[1]), "r"(a[2]), "r"(a[3]), "r"(b0), "r"(b1));
}
__device__ __forceinline__ void cp16(uint32_t dst, const void* src) {
    asm volatile("cp.async.cg.shared.global [%0], [%1], 16;" :: "r"(dst), "l"(src));
}
__device__ __forceinline__ void cp_commit() { asm volatile("cp.async.commit_group;"); }
__device__ __forceinline__ void cp_wait0()  { asm volatile("cp.async.wait_group 0;"); }
__device__ __forceinline__ void pref_l2(const void* p) {
    asm volatile("prefetch.global.L2 [%0];" :: "l"(p));
}
__device__ __forceinline__ float silu_f(float x) { return x / (1.0f + __expf(-x)); }

// ---------------- weight pre-split (fp16 hi/lo) ----------------
__global__ __launch_bounds__(256) void prep_w_kernel(const float* __restrict__ W0,
                                                     const float* __restrict__ W1,
                                                     const float* __restrict__ W2,
                                                     const float* __restrict__ W3,
                                                     const float* __restrict__ W4) {
    int i = blockIdx.x * 256 + threadIdx.x;
    int w = i >> 14, j = i & (D * D - 1);
    const float* W = (w == 0) ? W0 : (w == 1) ? W1 : (w == 2) ? W2 : (w == 3) ? W3 : W4;
    float x = W[j];
    __half h = __float2half_rn(x);
    g_Wh[i] = h;
    g_Wl[i] = __float2half_rn(x - __half2float(h));
}

// ---------------- tile loads ----------------
__device__ __forceinline__ void load_W_cp(__half* Wh, __half* Wl, int widx, int tid) {
    const __half* gh = g_Wh + widx * D * D;
    const __half* gl = g_Wl + widx * D * D;
    uint32_t dh = smem_u32(Wh), dl = smem_u32(Wl);
    #pragma unroll
    for (int i = tid; i < D * 16; i += 256) {
        int r = i >> 4, c = (i & 15) * 8;
        uint32_t o = (uint32_t)(r * LDS_T + c) * 2;
        cp16(dh + o, gh + r * D + c);
        cp16(dl + o, gl + r * D + c);
    }
}
__device__ __forceinline__ void load_X_f16(__half* Xs, const float* __restrict__ Xg, int tid) {
    #pragma unroll
    for (int i = tid; i < 64 * 32; i += 256) {
        int r = i >> 5, c = (i & 31) * 4;
        float4 v = *(const float4*)(Xg + (size_t)r * D + c);
        __half2 a = __floats2half2_rn(v.x, v.y);
        __half2 b = __floats2half2_rn(v.z, v.w);
        *(uint32_t*)(Xs + r * LDS_T + c)     = *(uint32_t*)&a;
        *(uint32_t*)(Xs + r * LDS_T + c + 2) = *(uint32_t*)&b;
    }
}

// ---------------- fp16 2-MMA GEMM core: 64x128 tile, 8 warps (4 rg x 2 cg) ----------------
#define KOFF ((uint32_t)(16 * LDS_T * 2))

__device__ __forceinline__ void gemm_mma64(const __half* Xs,
                                           const __half* Wh, const __half* Wl,
                                           int tid, float acc[8][4]) {
    int lane = tid & 31, w = tid >> 5;
    int rg = (w & 3) * 16, cg = (w >> 2) * 64;
    #pragma unroll
    for (int i = 0; i < 8; i++)
        #pragma unroll
        for (int j = 0; j < 4; j++) acc[i][j] = 0.0f;
    int l7 = lane & 7, lm = lane >> 3;
    int a_cad = (lm >> 1) << 3;
    uint32_t aA = smem_u32(Xs + (rg + l7 + ((lm & 1) << 3)) * LDS_T + a_cad);
    int b_krow = l7 + ((lm & 1) << 3);
    uint32_t bHb[4], bLb[4];
    #pragma unroll
    for (int nr = 0; nr < 4; nr++) {
        int col = cg + nr * 16 + a_cad;
        bHb[nr] = smem_u32(Wh + b_krow * LDS_T + col);
        bLb[nr] = smem_u32(Wl + b_krow * LDS_T + col);
    }
    #pragma unroll
    for (int k = 0; k < 8; k++) {
        uint32_t A[4];
        ldsm4(aA + (uint32_t)k * 32, A);
        #pragma unroll
        for (int nr = 0; nr < 4; nr++) {
            uint32_t BH[4], BL[4];
            ldsm4t(bHb[nr] + (uint32_t)k * KOFF, BH);
            ldsm4t(bLb[nr] + (uint32_t)k * KOFF, BL);
            mma16816(acc[2 * nr],     A, BH[0], BH[1]);
            mma16816(acc[2 * nr],     A, BL[0], BL[1]);
            mma16816(acc[2 * nr + 1], A, BH[2], BH[3]);
            mma16816(acc[2 * nr + 1], A, BL[2], BL[3]);
        }
    }
}

__device__ __forceinline__ void stage_acc(float* Cs, const float acc[8][4], int tid) {
    int lane = tid & 31, w = tid >> 5;
    int rg = (w & 3) * 16, cg = (w >> 2) * 64;
    int gid = lane >> 2, tid4 = lane & 3;
    #pragma unroll
    for (int nt = 0; nt < 8; nt++) {
        int col = cg + nt * 8 + tid4 * 2;
        int row = rg + gid;
        *(float2*)(Cs + row * LDC + col)       = make_float2(acc[nt][0], acc[nt][1]);
        *(float2*)(Cs + (row + 8) * LDC + col) = make_float2(acc[nt][2], acc[nt][3]);
    }
}
__device__ __forceinline__ void silu_ln(float v[4], const float gg[4], const float bb[4],
                                        float out[4]) {
    #pragma unroll
    for (int c = 0; c < 4; c++) v[c] = silu_f(v[c]);
    float s1 = v[0] + v[1] + v[2] + v[3];
    float s2 = v[0]*v[0] + v[1]*v[1] + v[2]*v[2] + v[3]*v[3];
    #pragma unroll
    for (int o = 16; o > 0; o >>= 1) {
        s1 += __shfl_xor_sync(0xFFFFFFFFu, s1, o);
        s2 += __shfl_xor_sync(0xFFFFFFFFu, s2, o);
    }
    float m   = s1 * (1.0f / D);
    float var = fmaxf(s2 * (1.0f / D) - m * m, 0.0f);
    float rs  = rsqrtf(var + 1e-5f);
    #pragma unroll
    for (int c = 0; c < 4; c++) out[c] = (v[c] - m) * rs * gg[c] + bb[c];
}

// smem layouts: [Wh 128x136][Wl 128x136][Xs 64x136] fp16; Cs (64x132 fp32) overlays Wh
#define SM_SINGLE ((2 * D * LDS_T + 64 * LDS_T) * 2)
// dual: [Wh1][Wl1][Wh2][Wl2][Xs]; Cs overlays Wh1
#define SM_DUAL   ((4 * D * LDS_T + 64 * LDS_T) * 2)

// ---------------- kernel 1: src @ W_s2e -> g_Ps ----------------
__global__ __launch_bounds__(256, 2) void proj_src_kernel(const float* __restrict__ src) {
    extern __shared__ char sm[];
    __half* Wh = (__half*)sm;
    __half* Wl = Wh + D * LDS_T;
    __half* Xs = Wl + D * LDS_T;
    float* Cs = (float*)sm;           // overlays Wh after MMA
    int tid = threadIdx.x;
    int row0 = blockIdx.x * 64;
    load_W_cp(Wh, Wl, 0, tid);
    cp_commit();
    load_X_f16(Xs, src + (size_t)row0 * D, tid);
    cp_wait0();
    __syncthreads();
    float acc[8][4];
    gemm_mma64(Xs, Wh, Wl, tid, acc);
    __syncthreads();
    stage_acc(Cs, acc, tid);
    __syncthreads();
    int tx = tid & 31, ty = tid >> 5;
    #pragma unroll
    for (int r = 0; r < 8; r++) {
        float4 v = *(float4*)(Cs + (ty * 8 + r) * LDC + tx * 4);
        *(float4*)(g_Ps + (size_t)(row0 + ty * 8 + r) * D + tx * 4) = v;
    }
}

// ---------------- kernel 2: tgt @ W_t2e -> g_Pt ; tgt @ W_t2t -> g_Ptt ----------------
__global__ __launch_bounds__(256) void proj_tgt_dual_kernel(const float* __restrict__ tgt) {
    extern __shared__ char sm[];
    __half* Wh1 = (__half*)sm;
    __half* Wl1 = Wh1 + D * LDS_T;
    __half* Wh2 = Wl1 + D * LDS_T;
    __half* Wl2 = Wh2 + D * LDS_T;
    __half* Xs  = Wl2 + D * LDS_T;
    float* Cs = (float*)sm;           // overlays Wh1 (only touched after gemm1)
    int tid = threadIdx.x;
    int row0 = blockIdx.x * 64;
    load_W_cp(Wh1, Wl1, 1, tid);
    load_W_cp(Wh2, Wl2, 4, tid);
    cp_commit();
    load_X_f16(Xs, tgt + (size_t)row0 * D, tid);
    cp_wait0();
    __syncthreads();
    int tx = tid & 31, ty = tid >> 5;
    {
        float acc[8][4];
        gemm_mma64(Xs, Wh1, Wl1, tid, acc);
        __syncthreads();
        stage_acc(Cs, acc, tid);
        __syncthreads();
        #pragma unroll
        for (int r = 0; r < 8; r++) {
            float4 v = *(float4*)(Cs + (ty * 8 + r) * LDC + tx * 4);
            *(float4*)(g_Pt + (size_t)(row0 + ty * 8 + r) * D + tx * 4) = v;
        }
        __syncthreads();
    }
    {
        float acc[8][4];
        gemm_mma64(Xs, Wh2, Wl2, tid, acc);
        __syncthreads();
        stage_acc(Cs, acc, tid);
        __syncthreads();
        #pragma unroll
        for (int r = 0; r < 8; r++) {
            float4 v = *(float4*)(Cs + (ty * 8 + r) * LDC + tx * 4);
            *(float4*)(g_Ptt + (size_t)(row0 + ty * 8 + r) * D + tx * 4) = v;
        }
    }
}

// ---------------- kernel 3: d_bond = LN(silu(bond@W_e2e + gather(Ps) + gather(Pt))) ----------------
__global__ __launch_bounds__(256, 2) void bond_kernel(const float* __restrict__ bond,
                                                      const float* __restrict__ g1,
                                                      const float* __restrict__ b1,
                                                      const int* __restrict__ src_order,
                                                      const int* __restrict__ tgt_order,
                                                      float* __restrict__ out0) {
    extern __shared__ char sm[];
    __half* Wh = (__half*)sm;
    __half* Wl = Wh + D * LDS_T;
    __half* Xs = Wl + D * LDS_T;
    float* Cs = (float*)sm;
    int tid = threadIdx.x;
    int tx = tid & 31, ty = tid >> 5;
    int row0 = blockIdx.x * 64;           // global row in [0, B*E)
    int b    = row0 / En;                 // tile never crosses batch (E % 64 == 0)
    int ebase = row0 - b * En;

    load_W_cp(Wh, Wl, 2, tid);            // W_e2e (async)
    cp_commit();
    load_X_f16(Xs, bond + (size_t)row0 * D, tid);

    // pre-MMA: prefetch Ps/Pt gather sectors into L2
    {
        int rr = tx >> 2, sec = tx & 3;
        int e = ebase + ty * 8 + rr;
        int so_ = src_order[e];
        int to_ = tgt_order[e];
        pref_l2(g_Ps + ((size_t)b * NSn + so_) * D + sec * 32);
        pref_l2(g_Pt + ((size_t)b * NTn + to_) * D + sec * 32);
    }

    cp_wait0();
    __syncthreads();
    float acc[8][4];
    gemm_mma64(Xs, Wh, Wl, tid, acc);
    __syncthreads();
    stage_acc(Cs, acc, tid);
    __syncthreads();

    float gg[4], bb[4];
    #pragma unroll
    for (int c = 0; c < 4; c++) { gg[c] = g1[tx * 4 + c]; bb[c] = b1[tx * 4 + c]; }

    #pragma unroll
    for (int r = 0; r < 8; r++) {
        int row = row0 + ty * 8 + r;
        int e   = ebase + ty * 8 + r;
        int so  = src_order[e];
        int to  = tgt_order[e];
        float4 cv = *(float4*)(Cs + (ty * 8 + r) * LDC + tx * 4);
        float4 ps = *(const float4*)(g_Ps + ((size_t)b * NSn + so) * D + tx * 4);
        float4 pt = *(const float4*)(g_Pt + ((size_t)b * NTn + to) * D + tx * 4);
        float v[4];
        v[0] = cv.x + ps.x + pt.x;
        v[1] = cv.y + ps.y + pt.y;
        v[2] = cv.z + ps.z + pt.z;
        v[3] = cv.w + ps.w + pt.w;
        float d[4];
        silu_ln(v, gg, bb, d);
        float4 xin = *(const float4*)(bond + (size_t)row * D + tx * 4);
        float4 db = {d[0], d[1], d[2], d[3]};
        float4 o0 = {xin.x + d[0], xin.y + d[1], xin.z + d[2], xin.w + d[3]};
        *(float4*)(g_db + (size_t)row * D + tx * 4) = db;
        *(float4*)(out0 + (size_t)row * D + tx * 4) = o0;
    }
}

// ---------------- kernel 4: bond_reduce = mean_k(coef * d_bond[edge_order]) ----------------
__global__ __launch_bounds__(256) void reduce_kernel(const int* __restrict__ edge_order,
                                                     const float* __restrict__ coef) {
    int tid  = threadIdx.x;
    int lane = tid & 31;
    int node = (blockIdx.x * blockDim.x + tid) >> 5;
    int b = node / NTn;
    int t = node - b * NTn;
    int   e_l = 0;
    float c_l = 0.0f;
    if (lane < Kc) {
        e_l = edge_order[t * Kc + lane];
        c_l = coef[t * Kc + lane];
    }
    float4 acc = {0.f, 0.f, 0.f, 0.f};
    #pragma unroll
    for (int k = 0; k < Kc; k++) {
        int   e = __shfl_sync(0xFFFFFFFFu, e_l, k);
        float c = __shfl_sync(0xFFFFFFFFu, c_l, k);
        float4 v = *(const float4*)(g_db + ((size_t)b * En + e) * D + lane * 4);
        acc.x += c * v.x;
        acc.y += c * v.y;
        acc.z += c * v.z;
        acc.w += c * v.w;
    }
    const float inv = 1.0f / Kc;
    acc.x *= inv; acc.y *= inv; acc.z *= inv; acc.w *= inv;
    *(float4*)(g_red + (size_t)node * D + lane * 4) = acc;
}

// ---------------- kernel 5: d_tgt = LN(silu(red@W_e2t + Ptt)) ; out = tgt + d_tgt ----------------
__global__ __launch_bounds__(256, 2) void tgt_kernel(const float* __restrict__ tgt,
                                                     const float* __restrict__ g2,
                                                     const float* __restrict__ b2,
                                                     float* __restrict__ out2) {
    extern __shared__ char sm[];
    __half* Wh = (__half*)sm;
    __half* Wl = Wh + D * LDS_T;
    __half* Xs = Wl + D * LDS_T;
    float* Cs = (float*)sm;
    int tid = threadIdx.x;
    int row0 = blockIdx.x * 64;
    load_W_cp(Wh, Wl, 3, tid);
    cp_commit();
    load_X_f16(Xs, g_red + (size_t)row0 * D, tid);
    cp_wait0();
    __syncthreads();
    float acc[8][4];
    gemm_mma64(Xs, Wh, Wl, tid, acc);
    __syncthreads();
    stage_acc(Cs, acc, tid);
    __syncthreads();

    int tx = tid & 31, ty = tid >> 5;
    float gg[4], bb[4];
    #pragma unroll
    for (int c = 0; c < 4; c++) { gg[c] = g2[tx * 4 + c]; bb[c] = b2[tx * 4 + c]; }
    #pragma unroll
    for (int r = 0; r < 8; r++) {
        int row = row0 + ty * 8 + r;
        float4 cv = *(float4*)(Cs + (ty * 8 + r) * LDC + tx * 4);
        float4 pt = *(const float4*)(g_Ptt + (size_t)row * D + tx * 4);
        float v[4];
        v[0] = cv.x + pt.x;
        v[1] = cv.y + pt.y;
        v[2] = cv.z + pt.z;
        v[3] = cv.w + pt.w;
        float d[4];
        silu_ln(v, gg, bb, d);
        float4 tin = *(const float4*)(tgt + (size_t)row * D + tx * 4);
        float4 o2 = {tin.x + d[0], tin.y + d[1], tin.z + d[2], tin.w + d[3]};
        *(float4*)(out2 + (size_t)row * D + tx * 4) = o2;
    }
}

// ---------------- launch ----------------
extern "C" void kernel_launch(void* const* d_in, const int* in_sizes, int n_in,
                              void* d_out, int out_size) {
    const float* bond  = (const float*)d_in[0];
    const float* src   = (const float*)d_in[1];
    const float* tgt   = (const float*)d_in[2];
    const float* W_s2e = (const float*)d_in[3];
    const float* W_t2e = (const float*)d_in[4];
    const float* W_e2e = (const float*)d_in[5];
    const float* ln1_g = (const float*)d_in[6];
    const float* ln1_b = (const float*)d_in[7];
    const float* W_e2t = (const float*)d_in[8];
    const float* W_t2t = (const float*)d_in[9];
    const float* ln2_g = (const float*)d_in[10];
    const float* ln2_b = (const float*)d_in[11];
    const float* coef  = (const float*)d_in[12];
    const int*   so    = (const int*)d_in[13];
    const int*   to    = (const int*)d_in[14];
    const int*   eo    = (const int*)d_in[15];

    float* out  = (float*)d_out;
    float* out0 = out;                                   // bond + d_bond   [B,E,D]
    float* out1 = out0 + (size_t)Bn * En * D;            // src passthrough [B,NS,D]
    float* out2 = out1 + (size_t)Bn * NSn * D;           // tgt + d_tgt     [B,NT,D]

    cudaFuncSetAttribute(proj_src_kernel,      cudaFuncAttributeMaxDynamicSharedMemorySize, SM_SINGLE);
    cudaFuncSetAttribute(proj_tgt_dual_kernel, cudaFuncAttributeMaxDynamicSharedMemorySize, SM_DUAL);
    cudaFuncSetAttribute(bond_kernel,          cudaFuncAttributeMaxDynamicSharedMemorySize, SM_SINGLE);
    cudaFuncSetAttribute(tgt_kernel,           cudaFuncAttributeMaxDynamicSharedMemorySize, SM_SINGLE);

    prep_w_kernel<<<320, 256>>>(W_s2e, W_t2e, W_e2e, W_e2t, W_t2t);

    proj_src_kernel<<<(Bn * NSn) / 64, 256, SM_SINGLE>>>(src);
    proj_tgt_dual_kernel<<<(Bn * NTn) / 64, 256, SM_DUAL>>>(tgt);

    cudaMemcpyAsync(out1, src, (size_t)Bn * NSn * D * sizeof(float),
                    cudaMemcpyDeviceToDevice, 0);

    bond_kernel<<<(Bn * En) / 64, 256, SM_SINGLE>>>(bond, ln1_g, ln1_b, so, to, out0);

    reduce_kernel<<<(Bn * NTn) / 8, 256>>>(eo, coef);

    tgt_kernel<<<(Bn * NTn) / 64, 256, SM_SINGLE>>>(tgt, ln2_g, ln2_b, out2);
}